// round 1
// baseline (speedup 1.0000x reference)
#include <cuda_runtime.h>
#include <cstdint>

#define BATCH 65536
#define DIN   256
#define HDIM  512
#define KDIM  768            // DIN + HDIM
#define NDIM  2048           // 4 * HDIM, gate-interleaved: n = 4*h + g

// Scratch (no cudaMalloc allowed): packed weights + fused bias
__device__ float g_Wpack[KDIM * NDIM];   // [k][n], tf32-rounded, row-major
__device__ float g_bias[NDIM];

__device__ __forceinline__ uint32_t f2tf32(float x) {
    uint32_t u;
    asm("cvt.rna.tf32.f32 %0, %1;" : "=r"(u) : "f"(x));
    return u;
}
__device__ __forceinline__ float tanh_ap(float x) {
    float y;
    asm("tanh.approx.f32 %0, %1;" : "=f"(y) : "f"(x));
    return y;
}
__device__ __forceinline__ float sigmoid_ap(float x) {
    return 0.5f * tanh_ap(0.5f * x) + 0.5f;
}

__device__ __forceinline__ void mma_tf32(float acc[4], const uint32_t a[4], const uint32_t b[2]) {
    asm volatile(
        "mma.sync.aligned.m16n8k8.row.col.f32.tf32.tf32.f32 "
        "{%0,%1,%2,%3}, {%4,%5,%6,%7}, {%8,%9}, {%0,%1,%2,%3};"
        : "+f"(acc[0]), "+f"(acc[1]), "+f"(acc[2]), "+f"(acc[3])
        : "r"(a[0]), "r"(a[1]), "r"(a[2]), "r"(a[3]),
          "r"(b[0]), "r"(b[1]));
}

// ---------------------------------------------------------------------------
// Pack: Wpack[k][4h+g] = (k<DIN ? U[g][k][h] : W[g][k-DIN][h]), tf32-rounded.
// bias[4h+g] = bU[g][h] + bW[g][h].
// ---------------------------------------------------------------------------
__global__ void pack_kernel(const float* __restrict__ U, const float* __restrict__ bU,
                            const float* __restrict__ W, const float* __restrict__ bW) {
    int idx = blockIdx.x * blockDim.x + threadIdx.x;
    const int total = KDIM * NDIM;
    for (int t = idx; t < total; t += gridDim.x * blockDim.x) {
        int k = t >> 11;        // / 2048
        int n = t & 2047;
        int h = n >> 2;
        int g = n & 3;
        float v = (k < DIN) ? U[((size_t)g * DIN + k) * HDIM + h]
                            : W[((size_t)g * HDIM + (k - DIN)) * HDIM + h];
        g_Wpack[t] = __uint_as_float(f2tf32(v));
    }
    if (idx < NDIM) {
        int h = idx >> 2, g = idx & 3;
        g_bias[idx] = bU[g * HDIM + h] + bW[g * HDIM + h];
    }
}

// ---------------------------------------------------------------------------
// Fused GEMM + LSTM epilogue.
// C[B, 2048] = [x | h_old] @ Wpack, tiles BM=128, BN=128, BK=32.
// 8 warps (2 M x 4 N), warp tile 64x32, m16n8k8 tf32 mma.
// Smem: As [2][128][36] (m-major, pad->conflict-free frag loads)
//       Bs [2][32][136] (k-major, pad->conflict-free frag loads)
//       Epilogue reuses smem as Cs[128][132].
// ---------------------------------------------------------------------------
#define AS_STRIDE 36
#define AS_STAGE  (128 * AS_STRIDE)
#define BS_STRIDE 136
#define BS_STAGE  (32 * BS_STRIDE)
#define CS_STRIDE 132
#define SMEM_FLOATS (2 * AS_STAGE + 2 * BS_STAGE)   // 17920 floats = 71680 B

__global__ void __launch_bounds__(256)
lstm_gemm_kernel(const float* __restrict__ x, const float* __restrict__ h_old,
                 const float* __restrict__ c_old, float* __restrict__ out) {
    extern __shared__ float sm[];
    float* As = sm;
    float* Bs = sm + 2 * AS_STAGE;

    const int tid  = threadIdx.x;
    const int lane = tid & 31;
    const int warp = tid >> 5;
    const int warpM = warp >> 2;     // 0..1
    const int warpN = warp & 3;      // 0..3

    const int bM = blockIdx.y * 128;
    const int bN = blockIdx.x * 128;

    float acc[4][4][4];
#pragma unroll
    for (int i = 0; i < 4; i++)
#pragma unroll
        for (int j = 0; j < 4; j++)
#pragma unroll
            for (int r = 0; r < 4; r++) acc[i][j][r] = 0.f;

    // Per-thread load coordinates
    // A: 4 x float4, f = t*256+tid, m=f>>3, kq=f&7  (row m, k-quad kq)
    // B: 4 x float4, f = t*256+tid, k=f>>5, nq=f&31
    float4 ra[4], rb[4];

#define LDG_A(KT_)                                                              \
    {                                                                           \
        int kbase = (KT_) * 32;                                                 \
        const float* src; int stride, kofs;                                     \
        if (kbase < DIN) { src = x; stride = DIN; kofs = kbase; }               \
        else             { src = h_old; stride = HDIM; kofs = kbase - DIN; }    \
        _Pragma("unroll")                                                       \
        for (int t = 0; t < 4; t++) {                                           \
            int f = t * 256 + tid;                                              \
            int m = f >> 3, kq = f & 7;                                         \
            ra[t] = *reinterpret_cast<const float4*>(                           \
                src + (size_t)(bM + m) * stride + kofs + kq * 4);               \
        }                                                                       \
    }

#define LDG_B(KT_)                                                              \
    {                                                                           \
        int kbase = (KT_) * 32;                                                 \
        _Pragma("unroll")                                                       \
        for (int t = 0; t < 4; t++) {                                           \
            int f = t * 256 + tid;                                              \
            int k = f >> 5, nq = f & 31;                                        \
            rb[t] = *reinterpret_cast<const float4*>(                           \
                &g_Wpack[(size_t)(kbase + k) * NDIM + bN + nq * 4]);            \
        }                                                                       \
    }

#define STS_AB(STAGE_)                                                          \
    {                                                                           \
        float* da = As + (STAGE_) * AS_STAGE;                                   \
        float* db = Bs + (STAGE_) * BS_STAGE;                                   \
        _Pragma("unroll")                                                       \
        for (int t = 0; t < 4; t++) {                                           \
            int f = t * 256 + tid;                                              \
            int m = f >> 3, kq = f & 7;                                         \
            float4 v;                                                           \
            v.x = __uint_as_float(f2tf32(ra[t].x));                             \
            v.y = __uint_as_float(f2tf32(ra[t].y));                             \
            v.z = __uint_as_float(f2tf32(ra[t].z));                             \
            v.w = __uint_as_float(f2tf32(ra[t].w));                             \
            *reinterpret_cast<float4*>(da + m * AS_STRIDE + kq * 4) = v;        \
            int k = f >> 5, nq = f & 31;                                        \
            *reinterpret_cast<float4*>(db + k * BS_STRIDE + nq * 4) = rb[t];    \
        }                                                                       \
    }

    LDG_A(0); LDG_B(0);
    STS_AB(0);
    __syncthreads();

    const int KT = KDIM / 32;   // 24
    for (int kt = 0; kt < KT; kt++) {
        int cur = kt & 1;
        int nxt = cur ^ 1;
        if (kt + 1 < KT) { LDG_A(kt + 1); LDG_B(kt + 1); }

        const float* Asc = As + cur * AS_STAGE;
        const float* Bsc = Bs + cur * BS_STAGE;
#pragma unroll
        for (int kk = 0; kk < 4; kk++) {
            uint32_t af[4][4];
            uint32_t bf[4][2];
            const int k0 = kk * 8 + (lane & 3);
            const int r0 = warpM * 64 + (lane >> 2);
#pragma unroll
            for (int mi = 0; mi < 4; mi++) {
                const float* ap = Asc + (r0 + mi * 16) * AS_STRIDE + k0;
                af[mi][0] = __float_as_uint(ap[0]);
                af[mi][1] = __float_as_uint(ap[8 * AS_STRIDE]);
                af[mi][2] = __float_as_uint(ap[4]);
                af[mi][3] = __float_as_uint(ap[8 * AS_STRIDE + 4]);
            }
            const int n0 = warpN * 32 + (lane >> 2);
#pragma unroll
            for (int nj = 0; nj < 4; nj++) {
                const float* bp = Bsc + k0 * BS_STRIDE + n0 + nj * 8;
                bf[nj][0] = __float_as_uint(bp[0]);
                bf[nj][1] = __float_as_uint(bp[4 * BS_STRIDE]);
            }
#pragma unroll
            for (int mi = 0; mi < 4; mi++)
#pragma unroll
                for (int nj = 0; nj < 4; nj++)
                    mma_tf32(acc[mi][nj], af[mi], bf[nj]);
        }
        if (kt + 1 < KT) { STS_AB(nxt); }
        __syncthreads();
    }

    // ---------------- Epilogue: through smem for coalesced I/O ----------------
    float* Cs = sm;   // [128][132], fits inside the 17920-float region
    {
        const int r0 = warpM * 64 + (lane >> 2);
        const int c0 = warpN * 32 + (lane & 3) * 2;
#pragma unroll
        for (int mi = 0; mi < 4; mi++)
#pragma unroll
            for (int nj = 0; nj < 4; nj++) {
                float* p = Cs + (r0 + mi * 16) * CS_STRIDE + c0 + nj * 8;
                *reinterpret_cast<float2*>(p) =
                    make_float2(acc[mi][nj][0], acc[mi][nj][1]);
                *reinterpret_cast<float2*>(p + 8 * CS_STRIDE) =
                    make_float2(acc[mi][nj][2], acc[mi][nj][3]);
            }
    }
    __syncthreads();

    float* out_h = out;
    float* out_c = out + (size_t)BATCH * HDIM;
#pragma unroll
    for (int it = 0; it < 16; it++) {
        int e = it * 256 + tid;
        int r  = e >> 5;        // 0..127
        int hl = e & 31;        // 0..31 local h
        float4 g4 = *reinterpret_cast<const float4*>(Cs + r * CS_STRIDE + hl * 4);
        float4 b4 = *reinterpret_cast<const float4*>(&g_bias[bN + hl * 4]);
        int hg = (bN >> 2) + hl;          // global h
        int rg = bM + r;                  // global row
        float gi = sigmoid_ap(g4.x + b4.x);
        float gf = sigmoid_ap(g4.y + b4.y);
        float go = sigmoid_ap(g4.z + b4.z);
        float gc = tanh_ap(g4.w + b4.w);
        float co = c_old[(size_t)rg * HDIM + hg];
        float cn = fmaf(gf, co, gi * gc);
        out_c[(size_t)rg * HDIM + hg] = cn;
        out_h[(size_t)rg * HDIM + hg] = go * tanh_ap(cn);
    }
}

// ---------------------------------------------------------------------------
extern "C" void kernel_launch(void* const* d_in, const int* in_sizes, int n_in,
                              void* d_out, int out_size) {
    const float* x     = (const float*)d_in[0];
    const float* h_old = (const float*)d_in[1];
    const float* c_old = (const float*)d_in[2];
    const float* U     = (const float*)d_in[3];
    const float* bU    = (const float*)d_in[4];
    const float* W     = (const float*)d_in[5];
    const float* bW    = (const float*)d_in[6];
    float* out = (float*)d_out;

    pack_kernel<<<512, 256>>>(U, bU, W, bW);

    cudaFuncSetAttribute(lstm_gemm_kernel,
                         cudaFuncAttributeMaxDynamicSharedMemorySize,
                         SMEM_FLOATS * sizeof(float));
    dim3 grid(NDIM / 128, BATCH / 128);   // (16, 512), N-fastest for L2 reuse of A
    lstm_gemm_kernel<<<grid, 256, SMEM_FLOATS * sizeof(float)>>>(x, h_old, c_old, out);
}

// round 3
// speedup vs baseline: 1.9510x; 1.9510x over previous
#include <cuda_runtime.h>
#include <cuda_fp16.h>
#include <cstdint>

#define BATCH 65536
#define DIN   256
#define HDIM  512
#define KDIM  768
#define NDIM  2048

#define BM 128
#define BN 256
#define BK 64
#define KT 12
#define STAGES 4
#define ASTG 16384                       // 128 rows x 128B
#define BSTG 32768                       // 256 rows x 128B
#define STG_BYTES (ASTG + BSTG)          // 49152
#define BIAS_OFF (STAGES * STG_BYTES)    // 196608
#define SMEM_BYTES (BIAS_OFF + BN * 4)   // 197632

// __device__ scratch (no cudaMalloc allowed)
__device__ __half g_Apack[(size_t)BATCH * KDIM];   // [b][k], k = [x | h], rn-rounded
__device__ __half g_Wpack[(size_t)NDIM * KDIM];    // [n][k], n = 4h+g, rn-rounded
__device__ float  g_bias[NDIM];

// ---------------- helpers ----------------
__device__ __forceinline__ uint32_t smem_u32(const void* p) {
    uint32_t a;
    asm("{ .reg .u64 t; cvta.to.shared.u64 t, %1; cvt.u32.u64 %0, t; }" : "=r"(a) : "l"(p));
    return a;
}
__device__ __forceinline__ float tanh_ap(float x) {
    float y; asm("tanh.approx.f32 %0, %1;" : "=f"(y) : "f"(x)); return y;
}
__device__ __forceinline__ float sig_ap(float x) { return 0.5f * tanh_ap(0.5f * x) + 0.5f; }

__device__ __forceinline__ void cp16(uint32_t d, const void* s) {
    asm volatile("cp.async.cg.shared.global [%0], [%1], 16;" :: "r"(d), "l"(s) : "memory");
}
__device__ __forceinline__ void cp_commit() {
    asm volatile("cp.async.commit_group;" ::: "memory");
}
#define CP_WAIT(N) asm volatile("cp.async.wait_group %0;" :: "n"(N) : "memory")

__device__ __forceinline__ void ldsm4(uint32_t r[4], uint32_t addr) {
    asm volatile("ldmatrix.sync.aligned.m8n8.x4.shared.b16 {%0,%1,%2,%3}, [%4];"
                 : "=r"(r[0]), "=r"(r[1]), "=r"(r[2]), "=r"(r[3]) : "r"(addr));
}
__device__ __forceinline__ void mma16816(float d[4], const uint32_t a[4],
                                         uint32_t b0, uint32_t b1) {
    asm volatile(
        "mma.sync.aligned.m16n8k16.row.col.f32.f16.f16.f32 "
        "{%0,%1,%2,%3},{%4,%5,%6,%7},{%8,%9},{%0,%1,%2,%3};"
        : "+f"(d[0]), "+f"(d[1]), "+f"(d[2]), "+f"(d[3])
        : "r"(a[0]), "r"(a[1]), "r"(a[2]), "r"(a[3]), "r"(b0), "r"(b1));
}

// ---------------------------------------------------------------------------
// pack A = [x | h] as fp16 [B][768] (16B chunks)
// ---------------------------------------------------------------------------
__global__ void pack_a_kernel(const float* __restrict__ x, const float* __restrict__ h) {
    const size_t nch = (size_t)BATCH * 96;   // 96 x 16B chunks per row
    for (size_t id = (size_t)blockIdx.x * blockDim.x + threadIdx.x; id < nch;
         id += (size_t)gridDim.x * blockDim.x) {
        size_t r = id / 96;
        int c = (int)(id % 96);
        const float* src = (c < 32) ? (x + r * DIN + c * 8) : (h + r * HDIM + (c - 32) * 8);
        float4 f0 = reinterpret_cast<const float4*>(src)[0];
        float4 f1 = reinterpret_cast<const float4*>(src)[1];
        __half2 h0 = __floats2half2_rn(f0.x, f0.y), h1 = __floats2half2_rn(f0.z, f0.w);
        __half2 h2 = __floats2half2_rn(f1.x, f1.y), h3 = __floats2half2_rn(f1.z, f1.w);
        uint4 v;
        v.x = *reinterpret_cast<uint32_t*>(&h0); v.y = *reinterpret_cast<uint32_t*>(&h1);
        v.z = *reinterpret_cast<uint32_t*>(&h2); v.w = *reinterpret_cast<uint32_t*>(&h3);
        reinterpret_cast<uint4*>(g_Apack + r * KDIM)[c] = v;
    }
}

// ---------------------------------------------------------------------------
// pack W: Wpack[n][k] fp16, n = 4h+g; bias[n] = bU+bW
// ---------------------------------------------------------------------------
__global__ void pack_w_kernel(const float* __restrict__ U, const float* __restrict__ bU,
                              const float* __restrict__ W, const float* __restrict__ bW) {
    int idx = blockIdx.x * blockDim.x + threadIdx.x;
    const int total = NDIM * KDIM;
    for (int t = idx; t < total; t += gridDim.x * blockDim.x) {
        int n = t / KDIM;
        int k = t - n * KDIM;
        int h = n >> 2, g = n & 3;
        float v = (k < DIN) ? U[((size_t)g * DIN + k) * HDIM + h]
                            : W[((size_t)g * HDIM + (k - DIN)) * HDIM + h];
        g_Wpack[t] = __float2half_rn(v);
    }
    if (idx < NDIM) {
        int h = idx >> 2, g = idx & 3;
        g_bias[idx] = bU[g * HDIM + h] + bW[g * HDIM + h];
    }
}

// ---------------------------------------------------------------------------
// GEMM + fused LSTM.  BM=128 x BN=256, BK=64, 4-stage cp.async, 16 warps.
// Warp grid 2(M) x 8(N); warp tile 64x32; m16n8k16 fp16 mma, ldmatrix frags.
// ---------------------------------------------------------------------------
__global__ void __launch_bounds__(512, 1)
lstm_gemm_kernel(const float* __restrict__ c_old, float* __restrict__ out) {
    extern __shared__ __align__(1024) char smem[];
    const uint32_t sb = smem_u32(smem);
    const int tid  = threadIdx.x;
    const int lane = tid & 31;
    const int warp = tid >> 5;
    const int warpM = warp & 1;      // 0..1
    const int warpN = warp >> 1;     // 0..7
    const int bM = blockIdx.y * BM;
    const int bN = blockIdx.x * BN;

    // bias to smem
    float* bs = reinterpret_cast<float*>(smem + BIAS_OFF);
    for (int i = tid; i < BN; i += 512) bs[i] = g_bias[bN + i];

    // producer mapping: 16B chunk = (row, c), swizzled SW128
    const __half* srcA[2]; uint32_t dstA[2];
#pragma unroll
    for (int i = 0; i < 2; i++) {
        int ch = tid + i * 512, r = ch >> 3, c = ch & 7;
        srcA[i] = g_Apack + (size_t)(bM + r) * KDIM + c * 8;
        dstA[i] = sb + r * 128 + (((uint32_t)c ^ (r & 7)) << 4);
    }
    const __half* srcB[4]; uint32_t dstB[4];
#pragma unroll
    for (int i = 0; i < 4; i++) {
        int ch = tid + i * 512, r = ch >> 3, c = ch & 7;
        srcB[i] = g_Wpack + (size_t)(bN + r) * KDIM + c * 8;
        dstB[i] = sb + ASTG + r * 128 + (((uint32_t)c ^ (r & 7)) << 4);
    }

#define ISSUE(KT_)                                                         \
    {                                                                      \
        uint32_t so = ((KT_) & 3) * STG_BYTES;                             \
        size_t ko = (size_t)(KT_) * BK;                                    \
        _Pragma("unroll")                                                  \
        for (int i = 0; i < 2; i++) cp16(dstA[i] + so, srcA[i] + ko);      \
        _Pragma("unroll")                                                  \
        for (int i = 0; i < 4; i++) cp16(dstB[i] + so, srcB[i] + ko);      \
    }

    // ldmatrix lane addressing (lane -> matrix row), precomputed
    uint32_t aOff[4], aSwz[4];
#pragma unroll
    for (int mi = 0; mi < 4; mi++) {
        int r = warpM * 64 + mi * 16 + ((lane >> 3) & 1) * 8 + (lane & 7);
        aOff[mi] = (uint32_t)r * 128u;
        aSwz[mi] = (uint32_t)(r & 7);
    }
    uint32_t bOff[2], bSwz[2];
#pragma unroll
    for (int p = 0; p < 2; p++) {
        int r = warpN * 32 + p * 16 + ((lane >> 3) & 1) * 8 + (lane & 7);
        bOff[p] = (uint32_t)ASTG + (uint32_t)r * 128u;
        bSwz[p] = (uint32_t)(r & 7);
    }
    const uint32_t cHi = (uint32_t)(lane >> 4);   // +16B col for matrices 2,3

    float acc[4][4][4];
#pragma unroll
    for (int a = 0; a < 4; a++)
#pragma unroll
        for (int b = 0; b < 4; b++)
#pragma unroll
            for (int c = 0; c < 4; c++) acc[a][b][c] = 0.f;

    ISSUE(0); cp_commit();
    ISSUE(1); cp_commit();
    ISSUE(2); cp_commit();

    for (int kt = 0; kt < KT; kt++) {
        CP_WAIT(2);
        __syncthreads();
        if (kt + 3 < KT) { ISSUE(kt + 3); }
        cp_commit();

        const uint32_t stg = sb + (uint32_t)(kt & 3) * STG_BYTES;
#pragma unroll
        for (int kk = 0; kk < 4; kk++) {
            const uint32_t cc = (uint32_t)kk * 2u + cHi;
            uint32_t af[4][4];
#pragma unroll
            for (int mi = 0; mi < 4; mi++)
                ldsm4(af[mi], stg + aOff[mi] + ((cc ^ aSwz[mi]) << 4));
            uint32_t bf[2][4];
#pragma unroll
            for (int p = 0; p < 2; p++)
                ldsm4(bf[p], stg + bOff[p] + ((cc ^ bSwz[p]) << 4));
#pragma unroll
            for (int mi = 0; mi < 4; mi++)
#pragma unroll
                for (int p = 0; p < 2; p++)
#pragma unroll
                    for (int j = 0; j < 2; j++)
                        mma16816(acc[mi][p * 2 + j], af[mi], bf[p][j], bf[p][j + 2]);
        }
    }

    // ---------------- fused LSTM epilogue (shfl pairing, no smem C) --------
    float* out_h = out;
    float* out_c = out + (size_t)BATCH * HDIM;
    const int rBase = bM + warpM * 64 + (lane >> 2) + ((lane & 1) ? 8 : 0);
    const int odd = lane & 1;
#pragma unroll
    for (int mi = 0; mi < 4; mi++)
#pragma unroll
        for (int p = 0; p < 2; p++)
#pragma unroll
            for (int j = 0; j < 2; j++) {
                float* a = acc[mi][p * 2 + j];
                float t0 = __shfl_xor_sync(0xFFFFFFFFu, a[0], 1);
                float t1 = __shfl_xor_sync(0xFFFFFFFFu, a[1], 1);
                float t2 = __shfl_xor_sync(0xFFFFFFFFu, a[2], 1);
                float t3 = __shfl_xor_sync(0xFFFFFFFFu, a[3], 1);
                int nb = warpN * 32 + p * 16 + j * 8 + 2 * (lane & 3);
                int hl = nb >> 2;                       // local h (0..63)
                float4 b4 = *reinterpret_cast<const float4*>(bs + hl * 4);
                int hg = (bN >> 2) + hl;
                int rg = rBase + mi * 16;
                float vi = odd ? t2 : a[0];
                float vf = odd ? t3 : a[1];
                float vo = odd ? a[2] : t0;
                float vc = odd ? a[3] : t1;
                float gi = sig_ap(vi + b4.x);
                float gf = sig_ap(vf + b4.y);
                float go = sig_ap(vo + b4.z);
                float gc = tanh_ap(vc + b4.w);
                float co = c_old[(size_t)rg * HDIM + hg];
                float cn = fmaf(gf, co, gi * gc);
                out_c[(size_t)rg * HDIM + hg] = cn;
                out_h[(size_t)rg * HDIM + hg] = go * tanh_ap(cn);
            }
}

// ---------------------------------------------------------------------------
extern "C" void kernel_launch(void* const* d_in, const int* in_sizes, int n_in,
                              void* d_out, int out_size) {
    const float* x     = (const float*)d_in[0];
    const float* h_old = (const float*)d_in[1];
    const float* c_old = (const float*)d_in[2];
    const float* U     = (const float*)d_in[3];
    const float* bU    = (const float*)d_in[4];
    const float* W     = (const float*)d_in[5];
    const float* bW    = (const float*)d_in[6];
    float* out = (float*)d_out;

    pack_a_kernel<<<2048, 512>>>(x, h_old);
    pack_w_kernel<<<1536, 256>>>(U, bU, W, bW);

    cudaFuncSetAttribute(lstm_gemm_kernel,
                         cudaFuncAttributeMaxDynamicSharedMemorySize, SMEM_BYTES);
    dim3 grid(NDIM / BN, BATCH / BM);   // (8, 512), N fastest -> A tiles L2-resident
    lstm_gemm_kernel<<<grid, 512, SMEM_BYTES>>>(c_old, out);
}

// round 4
// speedup vs baseline: 2.1082x; 1.0806x over previous
#include <cuda_runtime.h>
#include <cuda_fp16.h>
#include <cstdint>

#define BATCH 65536
#define DIN   256
#define HDIM  512
#define KDIM  768
#define NDIM  2048

#define BM 128
#define BN 128
#define BK 64
#define KT 12
#define STAGES 3
#define ASTG 16384                       // 128 rows x 128B
#define BSTG 16384                       // 128 rows x 128B
#define STG_BYTES (ASTG + BSTG)          // 32768
#define BIAS_OFF (STAGES * STG_BYTES)    // 98304
#define SMEM_BYTES (BIAS_OFF + BN * 4)   // 98816

// __device__ scratch (no cudaMalloc allowed)
__device__ __half g_Apack[(size_t)BATCH * KDIM];   // [b][k], k = [x | h], rn-rounded
__device__ __half g_Wpack[(size_t)NDIM * KDIM];    // [n][k], n = 4h+g, rn-rounded
__device__ float  g_bias[NDIM];

// ---------------- helpers ----------------
__device__ __forceinline__ uint32_t smem_u32(const void* p) {
    uint32_t a;
    asm("{ .reg .u64 t; cvta.to.shared.u64 t, %1; cvt.u32.u64 %0, t; }" : "=r"(a) : "l"(p));
    return a;
}
__device__ __forceinline__ float tanh_ap(float x) {
    float y; asm("tanh.approx.f32 %0, %1;" : "=f"(y) : "f"(x)); return y;
}
__device__ __forceinline__ float sig_ap(float x) { return 0.5f * tanh_ap(0.5f * x) + 0.5f; }

__device__ __forceinline__ void cp16(uint32_t d, const void* s) {
    asm volatile("cp.async.cg.shared.global [%0], [%1], 16;" :: "r"(d), "l"(s) : "memory");
}
__device__ __forceinline__ void cp_commit() {
    asm volatile("cp.async.commit_group;" ::: "memory");
}
#define CP_WAIT(N) asm volatile("cp.async.wait_group %0;" :: "n"(N) : "memory")

__device__ __forceinline__ void ldsm4(uint32_t r[4], uint32_t addr) {
    asm volatile("ldmatrix.sync.aligned.m8n8.x4.shared.b16 {%0,%1,%2,%3}, [%4];"
                 : "=r"(r[0]), "=r"(r[1]), "=r"(r[2]), "=r"(r[3]) : "r"(addr));
}
__device__ __forceinline__ void mma16816(float d[4], const uint32_t a[4],
                                         uint32_t b0, uint32_t b1) {
    asm volatile(
        "mma.sync.aligned.m16n8k16.row.col.f32.f16.f16.f32 "
        "{%0,%1,%2,%3},{%4,%5,%6,%7},{%8,%9},{%0,%1,%2,%3};"
        : "+f"(d[0]), "+f"(d[1]), "+f"(d[2]), "+f"(d[3])
        : "r"(a[0]), "r"(a[1]), "r"(a[2]), "r"(a[3]), "r"(b0), "r"(b1));
}

// ---------------------------------------------------------------------------
// pack A = [x | h] as fp16 [B][768] (16B chunks)
// ---------------------------------------------------------------------------
__global__ void pack_a_kernel(const float* __restrict__ x, const float* __restrict__ h) {
    const size_t nch = (size_t)BATCH * 96;   // 96 x 16B chunks per row
    for (size_t id = (size_t)blockIdx.x * blockDim.x + threadIdx.x; id < nch;
         id += (size_t)gridDim.x * blockDim.x) {
        size_t r = id / 96;
        int c = (int)(id % 96);
        const float* src = (c < 32) ? (x + r * DIN + c * 8) : (h + r * HDIM + (c - 32) * 8);
        float4 f0 = reinterpret_cast<const float4*>(src)[0];
        float4 f1 = reinterpret_cast<const float4*>(src)[1];
        __half2 h0 = __floats2half2_rn(f0.x, f0.y), h1 = __floats2half2_rn(f0.z, f0.w);
        __half2 h2 = __floats2half2_rn(f1.x, f1.y), h3 = __floats2half2_rn(f1.z, f1.w);
        uint4 v;
        v.x = *reinterpret_cast<uint32_t*>(&h0); v.y = *reinterpret_cast<uint32_t*>(&h1);
        v.z = *reinterpret_cast<uint32_t*>(&h2); v.w = *reinterpret_cast<uint32_t*>(&h3);
        reinterpret_cast<uint4*>(g_Apack + r * KDIM)[c] = v;
    }
}

// ---------------------------------------------------------------------------
// pack W: Wpack[n][k] fp16, n = 4h+g; bias[n] = bU+bW
// ---------------------------------------------------------------------------
__global__ void pack_w_kernel(const float* __restrict__ U, const float* __restrict__ bU,
                              const float* __restrict__ W, const float* __restrict__ bW) {
    int idx = blockIdx.x * blockDim.x + threadIdx.x;
    const int total = NDIM * KDIM;
    for (int t = idx; t < total; t += gridDim.x * blockDim.x) {
        int n = t / KDIM;
        int k = t - n * KDIM;
        int h = n >> 2, g = n & 3;
        float v = (k < DIN) ? U[((size_t)g * DIN + k) * HDIM + h]
                            : W[((size_t)g * HDIM + (k - DIN)) * HDIM + h];
        g_Wpack[t] = __float2half_rn(v);
    }
    if (idx < NDIM) {
        int h = idx >> 2, g = idx & 3;
        g_bias[idx] = bU[g * HDIM + h] + bW[g * HDIM + h];
    }
}

// ---------------------------------------------------------------------------
// GEMM + fused LSTM.  BM=128 x BN=128, BK=64, 3-stage cp.async, 8 warps,
// 2 CTAs/SM for cross-CTA smem/tensor overlap.
// Warp grid 2(M) x 4(N); warp tile 64x32; m16n8k16 fp16 mma, ldmatrix frags.
// ---------------------------------------------------------------------------
__global__ void __launch_bounds__(256, 2)
lstm_gemm_kernel(const float* __restrict__ c_old, float* __restrict__ out) {
    extern __shared__ __align__(1024) char smem[];
    const uint32_t sb = smem_u32(smem);
    const int tid  = threadIdx.x;
    const int lane = tid & 31;
    const int warp = tid >> 5;
    const int warpM = warp & 1;      // 0..1
    const int warpN = warp >> 1;     // 0..3
    const int bM = blockIdx.y * BM;
    const int bN = blockIdx.x * BN;

    // bias to smem
    float* bs = reinterpret_cast<float*>(smem + BIAS_OFF);
    for (int i = tid; i < BN; i += 256) bs[i] = g_bias[bN + i];

    // producer mapping: 16B chunk = (row, c), swizzled SW128
    const __half* srcA[4]; uint32_t dstA[4];
#pragma unroll
    for (int i = 0; i < 4; i++) {
        int ch = tid + i * 256, r = ch >> 3, c = ch & 7;
        srcA[i] = g_Apack + (size_t)(bM + r) * KDIM + c * 8;
        dstA[i] = sb + r * 128 + (((uint32_t)c ^ (r & 7)) << 4);
    }
    const __half* srcB[4]; uint32_t dstB[4];
#pragma unroll
    for (int i = 0; i < 4; i++) {
        int ch = tid + i * 256, r = ch >> 3, c = ch & 7;
        srcB[i] = g_Wpack + (size_t)(bN + r) * KDIM + c * 8;
        dstB[i] = sb + ASTG + r * 128 + (((uint32_t)c ^ (r & 7)) << 4);
    }

#define ISSUE(KT_)                                                         \
    {                                                                      \
        uint32_t so = (uint32_t)((KT_) % STAGES) * STG_BYTES;              \
        size_t ko = (size_t)(KT_) * BK;                                    \
        _Pragma("unroll")                                                  \
        for (int i = 0; i < 4; i++) cp16(dstA[i] + so, srcA[i] + ko);      \
        _Pragma("unroll")                                                  \
        for (int i = 0; i < 4; i++) cp16(dstB[i] + so, srcB[i] + ko);      \
    }

    // ldmatrix lane addressing (lane -> matrix row), precomputed
    uint32_t aOff[4], aSwz[4];
#pragma unroll
    for (int mi = 0; mi < 4; mi++) {
        int r = warpM * 64 + mi * 16 + ((lane >> 3) & 1) * 8 + (lane & 7);
        aOff[mi] = (uint32_t)r * 128u;
        aSwz[mi] = (uint32_t)(r & 7);
    }
    uint32_t bOff[2], bSwz[2];
#pragma unroll
    for (int p = 0; p < 2; p++) {
        int r = warpN * 32 + p * 16 + ((lane >> 3) & 1) * 8 + (lane & 7);
        bOff[p] = (uint32_t)ASTG + (uint32_t)r * 128u;
        bSwz[p] = (uint32_t)(r & 7);
    }
    const uint32_t cHi = (uint32_t)(lane >> 4);   // +16B col for matrices 2,3

    float acc[4][4][4];
#pragma unroll
    for (int a = 0; a < 4; a++)
#pragma unroll
        for (int b = 0; b < 4; b++)
#pragma unroll
            for (int c = 0; c < 4; c++) acc[a][b][c] = 0.f;

    ISSUE(0); cp_commit();
    ISSUE(1); cp_commit();

    for (int kt = 0; kt < KT; kt++) {
        CP_WAIT(1);
        __syncthreads();
        if (kt + 2 < KT) { ISSUE(kt + 2); }
        cp_commit();

        const uint32_t stg = sb + (uint32_t)(kt % STAGES) * STG_BYTES;
#pragma unroll
        for (int kk = 0; kk < 4; kk++) {
            const uint32_t cc = (uint32_t)kk * 2u + cHi;
            uint32_t af[4][4];
#pragma unroll
            for (int mi = 0; mi < 4; mi++)
                ldsm4(af[mi], stg + aOff[mi] + ((cc ^ aSwz[mi]) << 4));
            uint32_t bf[2][4];
#pragma unroll
            for (int p = 0; p < 2; p++)
                ldsm4(bf[p], stg + bOff[p] + ((cc ^ bSwz[p]) << 4));
#pragma unroll
            for (int mi = 0; mi < 4; mi++)
#pragma unroll
                for (int p = 0; p < 2; p++)
#pragma unroll
                    for (int j = 0; j < 2; j++)
                        mma16816(acc[mi][p * 2 + j], af[mi], bf[p][j], bf[p][j + 2]);
        }
        __syncthreads();
    }

    // ---------------- fused LSTM epilogue (shfl pairing, no smem C) --------
    float* out_h = out;
    float* out_c = out + (size_t)BATCH * HDIM;
    const int rBase = bM + warpM * 64 + (lane >> 2) + ((lane & 1) ? 8 : 0);
    const int odd = lane & 1;
#pragma unroll
    for (int mi = 0; mi < 4; mi++)
#pragma unroll
        for (int p = 0; p < 2; p++)
#pragma unroll
            for (int j = 0; j < 2; j++) {
                float* a = acc[mi][p * 2 + j];
                float t0 = __shfl_xor_sync(0xFFFFFFFFu, a[0], 1);
                float t1 = __shfl_xor_sync(0xFFFFFFFFu, a[1], 1);
                float t2 = __shfl_xor_sync(0xFFFFFFFFu, a[2], 1);
                float t3 = __shfl_xor_sync(0xFFFFFFFFu, a[3], 1);
                int nb = warpN * 32 + p * 16 + j * 8 + 2 * (lane & 3);
                int hl = nb >> 2;                       // local h (0..31)
                float4 b4 = *reinterpret_cast<const float4*>(bs + hl * 4);
                int hg = (bN >> 2) + hl;
                int rg = rBase + mi * 16;
                float vi = odd ? t2 : a[0];
                float vf = odd ? t3 : a[1];
                float vo = odd ? a[2] : t0;
                float vc = odd ? a[3] : t1;
                float gi = sig_ap(vi + b4.x);
                float gf = sig_ap(vf + b4.y);
                float go = sig_ap(vo + b4.z);
                float gc = tanh_ap(vc + b4.w);
                float co = c_old[(size_t)rg * HDIM + hg];
                float cn = fmaf(gf, co, gi * gc);
                out_c[(size_t)rg * HDIM + hg] = cn;
                out_h[(size_t)rg * HDIM + hg] = go * tanh_ap(cn);
            }
}

// ---------------------------------------------------------------------------
extern "C" void kernel_launch(void* const* d_in, const int* in_sizes, int n_in,
                              void* d_out, int out_size) {
    const float* x     = (const float*)d_in[0];
    const float* h_old = (const float*)d_in[1];
    const float* c_old = (const float*)d_in[2];
    const float* U     = (const float*)d_in[3];
    const float* bU    = (const float*)d_in[4];
    const float* W     = (const float*)d_in[5];
    const float* bW    = (const float*)d_in[6];
    float* out = (float*)d_out;

    pack_a_kernel<<<2048, 512>>>(x, h_old);
    pack_w_kernel<<<1536, 256>>>(U, bU, W, bW);

    cudaFuncSetAttribute(lstm_gemm_kernel,
                         cudaFuncAttributeMaxDynamicSharedMemorySize, SMEM_BYTES);
    dim3 grid(NDIM / BN, BATCH / BM);   // (16, 512), N fastest -> A tiles L2-resident
    lstm_gemm_kernel<<<grid, 256, SMEM_BYTES>>>(c_old, out);
}

// round 6
// speedup vs baseline: 2.1387x; 1.0145x over previous
#include <cuda_runtime.h>
#include <cuda_fp16.h>
#include <cstdint>

#define BATCH 65536
#define DIN   256
#define HDIM  512
#define KDIM  768
#define NDIM  2048

#define BM 128
#define BN 128
#define BK 64
#define KT 12
#define STAGES 3
#define ASTG 16384                       // 128 rows x 128B
#define BSTG 16384
#define STG_BYTES (ASTG + BSTG)          // 32768
#define BIAS_OFF (STAGES * STG_BYTES)    // 98304
#define SMEM_BYTES (BIAS_OFF + BN * 4)   // 98816

__device__ __half g_Apack[(size_t)BATCH * KDIM];   // [b][k], k = [x | h]
__device__ __half g_Wpack[(size_t)NDIM * KDIM];    // [n][k], n = 4h+g
__device__ float  g_bias[NDIM];

// ---------------- helpers ----------------
__device__ __forceinline__ uint32_t smem_u32(const void* p) {
    uint32_t a;
    asm("{ .reg .u64 t; cvta.to.shared.u64 t, %1; cvt.u32.u64 %0, t; }" : "=r"(a) : "l"(p));
    return a;
}
__device__ __forceinline__ float tanh_ap(float x) {
    float y; asm("tanh.approx.f32 %0, %1;" : "=f"(y) : "f"(x)); return y;
}
__device__ __forceinline__ float sig_ap(float x) { return 0.5f * tanh_ap(0.5f * x) + 0.5f; }

__device__ __forceinline__ void cp16(uint32_t d, const void* s) {
    asm volatile("cp.async.cg.shared.global [%0], [%1], 16;" :: "r"(d), "l"(s) : "memory");
}
__device__ __forceinline__ void cp_commit() {
    asm volatile("cp.async.commit_group;" ::: "memory");
}
#define CP_WAIT(N) asm volatile("cp.async.wait_group %0;" :: "n"(N) : "memory")

__device__ __forceinline__ void ldsm4(uint32_t r[4], uint32_t addr) {
    asm volatile("ldmatrix.sync.aligned.m8n8.x4.shared.b16 {%0,%1,%2,%3}, [%4];"
                 : "=r"(r[0]), "=r"(r[1]), "=r"(r[2]), "=r"(r[3]) : "r"(addr));
}
__device__ __forceinline__ void mma16816(float d[4], const uint32_t a[4],
                                         uint32_t b0, uint32_t b1) {
    asm volatile(
        "mma.sync.aligned.m16n8k16.row.col.f32.f16.f16.f32 "
        "{%0,%1,%2,%3},{%4,%5,%6,%7},{%8,%9},{%0,%1,%2,%3};"
        : "+f"(d[0]), "+f"(d[1]), "+f"(d[2]), "+f"(d[3])
        : "r"(a[0]), "r"(a[1]), "r"(a[2]), "r"(a[3]), "r"(b0), "r"(b1));
}

// ---------------------------------------------------------------------------
__global__ void pack_a_kernel(const float* __restrict__ x, const float* __restrict__ h) {
    const size_t nch = (size_t)BATCH * 96;
    for (size_t id = (size_t)blockIdx.x * blockDim.x + threadIdx.x; id < nch;
         id += (size_t)gridDim.x * blockDim.x) {
        size_t r = id / 96;
        int c = (int)(id % 96);
        const float* src = (c < 32) ? (x + r * DIN + c * 8) : (h + r * HDIM + (c - 32) * 8);
        float4 f0 = reinterpret_cast<const float4*>(src)[0];
        float4 f1 = reinterpret_cast<const float4*>(src)[1];
        __half2 h0 = __floats2half2_rn(f0.x, f0.y), h1 = __floats2half2_rn(f0.z, f0.w);
        __half2 h2 = __floats2half2_rn(f1.x, f1.y), h3 = __floats2half2_rn(f1.z, f1.w);
        uint4 v;
        v.x = *reinterpret_cast<uint32_t*>(&h0); v.y = *reinterpret_cast<uint32_t*>(&h1);
        v.z = *reinterpret_cast<uint32_t*>(&h2); v.w = *reinterpret_cast<uint32_t*>(&h3);
        reinterpret_cast<uint4*>(g_Apack + r * KDIM)[c] = v;
    }
}

__global__ void pack_w_kernel(const float* __restrict__ U, const float* __restrict__ bU,
                              const float* __restrict__ W, const float* __restrict__ bW) {
    int idx = blockIdx.x * blockDim.x + threadIdx.x;
    const int total = NDIM * KDIM;
    for (int t = idx; t < total; t += gridDim.x * blockDim.x) {
        int n = t / KDIM;
        int k = t - n * KDIM;
        int h = n >> 2, g = n & 3;
        float v = (k < DIN) ? U[((size_t)g * DIN + k) * HDIM + h]
                            : W[((size_t)g * HDIM + (k - DIN)) * HDIM + h];
        g_Wpack[t] = __float2half_rn(v);
    }
    if (idx < NDIM) {
        int h = idx >> 2, g = idx & 3;
        g_bias[idx] = bU[g * HDIM + h] + bW[g * HDIM + h];
    }
}

// ---------------------------------------------------------------------------
// GEMM + fused LSTM.  BM=128 x BN=128, BK=64, 3-stage cp.async, 8 warps,
// 2 CTAs/SM; single barrier per k-tile; minimal addressing registers.
// ---------------------------------------------------------------------------
__global__ void __launch_bounds__(256, 2)
lstm_gemm_kernel(const float* __restrict__ c_old, float* __restrict__ out) {
    extern __shared__ __align__(1024) char smem[];
    const uint32_t sb = smem_u32(smem);
    const int tid  = threadIdx.x;
    const int lane = tid & 31;
    const int warp = tid >> 5;
    const int warpM = warp & 1;
    const int warpN = warp >> 1;
    const int bM = blockIdx.y * BM;
    const int bN = blockIdx.x * BN;

    float* bs = reinterpret_cast<float*>(smem + BIAS_OFF);
    for (int i = tid; i < BN; i += 256) bs[i] = g_bias[bN + i];

    // producer bases: thread owns (row r = tid>>3 (+32*i), chunk c = tid&7)
    const int pr = tid >> 3;
    const int pc = tid & 7;
    const __half* srcA0 = g_Apack + (size_t)(bM + pr) * KDIM + pc * 8;
    const __half* srcB0 = g_Wpack + (size_t)(bN + pr) * KDIM + pc * 8;
    const uint32_t dstA0 = sb + pr * 128 + (((uint32_t)pc ^ (pr & 7)) << 4);
    const uint32_t dstB0 = dstA0 + ASTG;   // same row/chunk pattern

#define ISSUE(KT_)                                                              \
    {                                                                           \
        uint32_t so = (uint32_t)((KT_) % STAGES) * STG_BYTES;                   \
        size_t ko = (size_t)(KT_) * BK;                                         \
        _Pragma("unroll")                                                       \
        for (int i = 0; i < 4; i++)                                             \
            cp16(dstA0 + so + i * 32 * 128, srcA0 + ko + (size_t)i * 32 * KDIM);\
        _Pragma("unroll")                                                       \
        for (int i = 0; i < 4; i++)                                             \
            cp16(dstB0 + so + i * 32 * 128, srcB0 + ko + (size_t)i * 32 * KDIM);\
    }

    // consumer LDSM bases: swizzle invariant under +16 rows
    const int lr = ((lane >> 3) & 1) * 8 + (lane & 7);
    const uint32_t aBase = (uint32_t)(warpM * 64 + lr) * 128u;
    const uint32_t aSwz  = (uint32_t)((warpM * 64 + lr) & 7);
    const uint32_t bBase = (uint32_t)ASTG + (uint32_t)(warpN * 32 + lr) * 128u;
    const uint32_t bSwz  = (uint32_t)((warpN * 32 + lr) & 7);
    const uint32_t cHi   = (uint32_t)(lane >> 4);

    float acc[4][4][4];
#pragma unroll
    for (int a = 0; a < 4; a++)
#pragma unroll
        for (int b = 0; b < 4; b++)
#pragma unroll
            for (int c = 0; c < 4; c++) acc[a][b][c] = 0.f;

    ISSUE(0); cp_commit();
    ISSUE(1); cp_commit();

    for (int kt = 0; kt < KT; kt++) {
        CP_WAIT(1);
        __syncthreads();
        if (kt + 2 < KT) { ISSUE(kt + 2); }
        cp_commit();

        const uint32_t stg = sb + (uint32_t)(kt % STAGES) * STG_BYTES;
#pragma unroll
        for (int kk = 0; kk < 4; kk++) {
            const uint32_t cc = (uint32_t)kk * 2u + cHi;
            uint32_t af[4][4];
#pragma unroll
            for (int mi = 0; mi < 4; mi++)
                ldsm4(af[mi], stg + aBase + mi * 16 * 128 + ((cc ^ aSwz) << 4));
            uint32_t bf[2][4];
#pragma unroll
            for (int p = 0; p < 2; p++)
                ldsm4(bf[p], stg + bBase + p * 16 * 128 + ((cc ^ bSwz) << 4));
#pragma unroll
            for (int mi = 0; mi < 4; mi++)
#pragma unroll
                for (int p = 0; p < 2; p++)
#pragma unroll
                    for (int j = 0; j < 2; j++)
                        mma16816(acc[mi][p * 2 + j], af[mi], bf[p][j], bf[p][j + 2]);
        }
    }

    // ---------------- fused LSTM epilogue (shfl pairing) -------------------
    float* out_h = out;
    float* out_c = out + (size_t)BATCH * HDIM;
    const int rBase = bM + warpM * 64 + (lane >> 2) + ((lane & 1) ? 8 : 0);
    const int odd = lane & 1;
#pragma unroll
    for (int mi = 0; mi < 4; mi++)
#pragma unroll
        for (int p = 0; p < 2; p++)
#pragma unroll
            for (int j = 0; j < 2; j++) {
                float* a = acc[mi][p * 2 + j];
                float t0 = __shfl_xor_sync(0xFFFFFFFFu, a[0], 1);
                float t1 = __shfl_xor_sync(0xFFFFFFFFu, a[1], 1);
                float t2 = __shfl_xor_sync(0xFFFFFFFFu, a[2], 1);
                float t3 = __shfl_xor_sync(0xFFFFFFFFu, a[3], 1);
                int nb = warpN * 32 + p * 16 + j * 8 + 2 * (lane & 3);
                int hl = nb >> 2;
                float4 b4 = *reinterpret_cast<const float4*>(bs + hl * 4);
                int hg = (bN >> 2) + hl;
                int rg = rBase + mi * 16;
                float vi = odd ? t2 : a[0];
                float vf = odd ? t3 : a[1];
                float vo = odd ? a[2] : t0;
                float vc = odd ? a[3] : t1;
                float gi = sig_ap(vi + b4.x);
                float gf = sig_ap(vf + b4.y);
                float go = sig_ap(vo + b4.z);
                float gc = tanh_ap(vc + b4.w);
                float co = c_old[(size_t)rg * HDIM + hg];
                float cn = fmaf(gf, co, gi * gc);
                out_c[(size_t)rg * HDIM + hg] = cn;
                out_h[(size_t)rg * HDIM + hg] = go * tanh_ap(cn);
            }
}

// ---------------------------------------------------------------------------
extern "C" void kernel_launch(void* const* d_in, const int* in_sizes, int n_in,
                              void* d_out, int out_size) {
    const float* x     = (const float*)d_in[0];
    const float* h_old = (const float*)d_in[1];
    const float* c_old = (const float*)d_in[2];
    const float* U     = (const float*)d_in[3];
    const float* bU    = (const float*)d_in[4];
    const float* W     = (const float*)d_in[5];
    const float* bW    = (const float*)d_in[6];
    float* out = (float*)d_out;

    pack_a_kernel<<<2048, 512>>>(x, h_old);
    pack_w_kernel<<<1536, 256>>>(U, bU, W, bW);

    cudaFuncSetAttribute(lstm_gemm_kernel,
                         cudaFuncAttributeMaxDynamicSharedMemorySize, SMEM_BYTES);
    dim3 grid(NDIM / BN, BATCH / BM);   // (16, 512)
    lstm_gemm_kernel<<<grid, 256, SMEM_BYTES>>>(c_old, out);
}